// round 6
// baseline (speedup 1.0000x reference)
#include <cuda_runtime.h>
#include <cstdint>
#include <cstddef>

#define D_DIM 64
#define KNB   32          // neighbors per node
#define NB    48          // nodes per block
#define TPB   128         // threads per block
#define XPAD  66          // padded row stride (floats) for bank-conflict-free x reads

// Global accumulator for stage-2 column-wise max (int bits of nonneg floats).
// init=0 acts as the relu floor: max(0, max_n h2) == max_n relu(h2).
__device__ int g_max_bits[64];

__global__ void init_kernel() {
    if (threadIdx.x < 64) g_max_bits[threadIdx.x] = 0;
}

__device__ __forceinline__ void cp_async8(void* dst, const void* src) {
    unsigned s = (unsigned)__cvta_generic_to_shared(dst);
    asm volatile("cp.async.ca.shared.global [%0], [%1], 8;" :: "r"(s), "l"(src) : "memory");
}
__device__ __forceinline__ void cp_commit() {
    asm volatile("cp.async.commit_group;" ::: "memory");
}

// Fused: stage-1 pooling aggregation + emb1 + stage-2 pooling into global max.
// Per block: 48 nodes. Thread (tn,tc) computes 3 nodes x 8 output cols.
extern "C" __global__ void __launch_bounds__(TPB)
stage1_kernel(const float* __restrict__ xs, const float* __restrict__ xnb,
              const float* __restrict__ W1, const float* __restrict__ b1,
              const float* __restrict__ E1, const float* __restrict__ W2,
              const float* __restrict__ b2, int n)
{
    __shared__ float sW[64 * 64];        // sW[d*64+o] = W1[o][d] (transposed)
    __shared__ float sB[64];
    __shared__ float sX[2 * NB * XPAD];  // double-buffered row stage; reused by epilogue
    __shared__ int   sH[64];             // block-level stage-2 max

    const int tid  = threadIdx.x;
    const int tn   = tid >> 3;           // 0..15 (node group of 3)
    const int tc   = tid & 7;            // 0..7  (col group of 8)
    const int base = blockIdx.x * NB;

    // Load W1 transposed + bias; init block max.
    for (int i = tid; i < 4096; i += TPB) {
        int o = i >> 6, d = i & 63;
        sW[d * 64 + o] = W1[i];
    }
    if (tid < 64) { sB[tid] = b1[tid]; sH[tid] = 0; }

    // Stage row-position rp (0..31 = neighbor k, 32 = self) for all NB nodes.
    auto stage = [&](int rp, int buf) {
        float* dstb = sX + buf * (NB * XPAD);
        #pragma unroll
        for (int k2 = 0; k2 < 12; ++k2) {
            int ci   = tid + k2 * TPB;      // 0..1535 (float2 chunks)
            int node = ci >> 5;             // 0..47
            int d2   = (ci & 31) * 2;       // 0..62 step 2
            int gn   = base + node; if (gn >= n) gn = n - 1;
            const float* src = (rp < KNB)
                ? (xnb + ((size_t)gn * KNB + rp) * D_DIM + d2)
                : (xs + (size_t)gn * D_DIM + d2);
            cp_async8(&dstb[node * XPAD + d2], src);
        }
        cp_commit();
    };

    stage(0, 0);

    __syncthreads();   // sW/sB visible
    float bj[8];
    #pragma unroll
    for (int j = 0; j < 8; ++j) bj[j] = sB[tc * 8 + j];

    float m[3][8];
    #pragma unroll
    for (int i = 0; i < 3; ++i)
        #pragma unroll
        for (int j = 0; j < 8; ++j) m[i][j] = -3.0e38f;

    for (int rp = 0; rp <= KNB; ++rp) {
        const int cur = rp & 1;
        if (rp < KNB) {
            stage(rp + 1, cur ^ 1);
            asm volatile("cp.async.wait_group 1;" ::: "memory");
        } else {
            asm volatile("cp.async.wait_group 0;" ::: "memory");
        }
        __syncthreads();

        const float* xb = sX + cur * (NB * XPAD);
        float y[3][8];
        #pragma unroll
        for (int i = 0; i < 3; ++i)
            #pragma unroll
            for (int j = 0; j < 8; ++j) y[i][j] = bj[j];

        #pragma unroll 8
        for (int d = 0; d < 64; ++d) {
            const float4 wa = *(const float4*)(sW + d * 64 + (tc << 3));
            const float4 wb = *(const float4*)(sW + d * 64 + (tc << 3) + 4);
            float xv[3];
            #pragma unroll
            for (int i = 0; i < 3; ++i) xv[i] = xb[(tn * 3 + i) * XPAD + d];
            #pragma unroll
            for (int i = 0; i < 3; ++i) {
                y[i][0] = fmaf(xv[i], wa.x, y[i][0]);
                y[i][1] = fmaf(xv[i], wa.y, y[i][1]);
                y[i][2] = fmaf(xv[i], wa.z, y[i][2]);
                y[i][3] = fmaf(xv[i], wa.w, y[i][3]);
                y[i][4] = fmaf(xv[i], wb.x, y[i][4]);
                y[i][5] = fmaf(xv[i], wb.y, y[i][5]);
                y[i][6] = fmaf(xv[i], wb.z, y[i][6]);
                y[i][7] = fmaf(xv[i], wb.w, y[i][7]);
            }
        }
        #pragma unroll
        for (int i = 0; i < 3; ++i)
            #pragma unroll
            for (int j = 0; j < 8; ++j) m[i][j] = fmaxf(m[i][j], y[i][j]);
        __syncthreads();   // protect buffer reuse next iteration
    }

    // ---- epilogue: aggr -> emb1 (l2norm) -> h2 -> block max -> global max ----
    float* aggrb = sX;                       // [NB][XPAD], relu(max) per node
    #pragma unroll
    for (int i = 0; i < 3; ++i)
        #pragma unroll
        for (int j = 0; j < 8; ++j)
            aggrb[(tn * 3 + i) * XPAD + tc * 8 + j] = fmaxf(m[i][j], 0.0f);
    __syncthreads();

    const int warp = tid >> 5, lane = tid & 31;
    float* embw = sX + NB * XPAD + warp * 80;   // per-warp emb1 buffer (8B aligned)

    for (int t = 0; t < NB / 4; ++t) {
        const int node = warp + t * 4;
        const int gn = base + node;
        if (gn < n) {                         // uniform per warp
            // emb1 pre-activation: two output rows per lane (o = lane, lane+32)
            float a0 = 0.f, a1 = 0.f;
            const float* e0r = E1 + lane * 64;
            const float* e1r = E1 + (lane + 32) * 64;
            const float* ab  = aggrb + node * XPAD;
            #pragma unroll 8
            for (int d = 0; d < 64; d += 2) {
                float2 av = *(const float2*)&ab[d];
                float2 p0 = __ldg((const float2*)&e0r[d]);
                float2 p1 = __ldg((const float2*)&e1r[d]);
                a0 += av.x * p0.x + av.y * p0.y;
                a1 += av.x * p1.x + av.y * p1.y;
            }
            a0 = fmaxf(a0, 0.f); a1 = fmaxf(a1, 0.f);
            float s = a0 * a0 + a1 * a1;
            #pragma unroll
            for (int off = 16; off; off >>= 1) s += __shfl_xor_sync(0xffffffffu, s, off);
            const float inv = (s > 0.f) ? (1.0f / sqrtf(s)) : 1.0f;
            embw[lane]      = a0 * inv;
            embw[lane + 32] = a1 * inv;
            __syncwarp();

            // stage-2 pre-activation h2 = W2 @ emb1 + b2
            float h0 = __ldg(&b2[lane]), h1 = __ldg(&b2[lane + 32]);
            const float* w0r = W2 + lane * 64;
            const float* w1r = W2 + (lane + 32) * 64;
            #pragma unroll 8
            for (int d = 0; d < 64; d += 2) {
                float2 ev = *(const float2*)&embw[d];
                float2 p0 = __ldg((const float2*)&w0r[d]);
                float2 p1 = __ldg((const float2*)&w1r[d]);
                h0 += ev.x * p0.x + ev.y * p0.y;
                h1 += ev.x * p1.x + ev.y * p1.y;
            }
            atomicMax(&sH[lane],      __float_as_int(h0));
            atomicMax(&sH[lane + 32], __float_as_int(h1));
            __syncwarp();   // all lanes done with embw before next node reuses it
        }
    }
    __syncthreads();
    if (tid < 64) atomicMax(&g_max_bits[tid], sH[tid]);
}

// Final tiny stage: aggr2 -> emb2 (l2norm) -> regressor -> scalar out.
extern "C" __global__ void finalize_kernel(const float* __restrict__ E2,
                                           const float* __restrict__ rW1,
                                           const float* __restrict__ rb1,
                                           const float* __restrict__ rW2,
                                           const float* __restrict__ rb2,
                                           float* __restrict__ out)
{
    __shared__ float sa[64], se[64];
    __shared__ float red[2];
    const int tid = threadIdx.x;   // 64 threads

    sa[tid] = __int_as_float(g_max_bits[tid]);   // = aggr2 (>= 0 by construction)
    __syncthreads();

    // emb2 pre-activation
    float acc = 0.f;
    const float* er = E2 + tid * 64;
    #pragma unroll 8
    for (int d = 0; d < 64; ++d) acc += er[d] * sa[d];
    acc = fmaxf(acc, 0.f);

    float s = acc * acc;
    #pragma unroll
    for (int off = 16; off; off >>= 1) s += __shfl_xor_sync(0xffffffffu, s, off);
    if ((tid & 31) == 0) red[tid >> 5] = s;
    __syncthreads();
    const float stot = red[0] + red[1];
    const float inv = (stot > 0.f) ? (1.0f / sqrtf(stot)) : 1.0f;
    se[tid] = acc * inv;
    __syncthreads();

    // regressor hidden layer
    float h = rb1[tid];
    const float* wr = rW1 + tid * 64;
    #pragma unroll 8
    for (int d = 0; d < 64; ++d) h += wr[d] * se[d];
    h = fmaxf(h, 0.f);

    float v = h * rW2[tid];
    #pragma unroll
    for (int off = 16; off; off >>= 1) v += __shfl_xor_sync(0xffffffffu, v, off);
    if ((tid & 31) == 0) red[tid >> 5] = v;
    __syncthreads();
    if (tid == 0) out[0] = red[0] + red[1] + rb2[0];
}

extern "C" void kernel_launch(void* const* d_in, const int* in_sizes, int n_in,
                              void* d_out, int out_size)
{
    const float* xs  = (const float*)d_in[0];   // x_self      [N,64]
    const float* xnb = (const float*)d_in[1];   // x_neighbors [N,32,64]
    const float* W1  = (const float*)d_in[2];   // aggr1_W [64,64]
    const float* b1  = (const float*)d_in[3];   // aggr1_b [64]
    const float* E1  = (const float*)d_in[4];   // emb1_W  [64,64]
    const float* W2  = (const float*)d_in[5];   // aggr2_W [64,64]
    const float* b2  = (const float*)d_in[6];   // aggr2_b [64]
    const float* E2  = (const float*)d_in[7];   // emb2_W  [64,64]
    const float* rW1 = (const float*)d_in[8];   // reg_W1 [64,64]
    const float* rb1 = (const float*)d_in[9];   // reg_b1 [64]
    const float* rW2 = (const float*)d_in[10];  // reg_W2 [1,64]
    const float* rb2 = (const float*)d_in[11];  // reg_b2 [1]

    const int n = in_sizes[0] / D_DIM;
    const int blocks = (n + NB - 1) / NB;

    init_kernel<<<1, 64>>>();
    stage1_kernel<<<blocks, TPB>>>(xs, xnb, W1, b1, E1, W2, b2, n);
    finalize_kernel<<<1, 64>>>(E2, rW1, rb1, rW2, rb2, (float*)d_out);
}

// round 9
// speedup vs baseline: 1.4169x; 1.4169x over previous
#include <cuda_runtime.h>
#include <cuda_bf16.h>
#include <cstdint>
#include <cstddef>

#define NPC  32            // nodes per CTA
#define TPB  256
#define KNB  32

// ---- dynamic SMEM layout (bytes) ----
#define SM_BIAS   0                       // f32[64]
#define SM_SH     256                     // int[64]
#define SM_EMBW   512                     // 8 warps x 80 f32 (2560B)
#define SM_BHI    3072                    // W1 hi: [64][72] bf16 (9216B)
#define SM_BLO    12288                   // W1 lo: [64][72] bf16 (9216B)
#define SM_NBMAX  21504                   // f32[32][66] (8448B)
#define SM_AHI    29952                   // A hi: [256][72] bf16 (36864B)
#define SM_ALO    66816                   // A lo: [256][72] bf16 (36864B)
#define SM_TOTAL  103680
// aliases (regions of A that are free when used):
#define SM_AGGR   SM_AHI                  // f32[32][66] after self-MMA done
#define SM_HSELF  (SM_ALO + 128*144)      // f32[32][66] in Alo rows >=128 (self MMA reads rows 0..31)

#define ASTRIDE 72                        // bf16 elems per row (144B)

__device__ int g_max_bits[64];
__global__ void init_kernel() { if (threadIdx.x < 64) g_max_bits[threadIdx.x] = 0; }

__device__ __forceinline__ void mma16816(float* d,
                                         uint32_t a0, uint32_t a1, uint32_t a2, uint32_t a3,
                                         uint32_t b0, uint32_t b1) {
    asm volatile(
        "mma.sync.aligned.m16n8k16.row.col.f32.bf16.bf16.f32 "
        "{%0,%1,%2,%3}, {%4,%5,%6,%7}, {%8,%9}, {%0,%1,%2,%3};"
        : "+f"(d[0]), "+f"(d[1]), "+f"(d[2]), "+f"(d[3])
        : "r"(a0), "r"(a1), "r"(a2), "r"(a3), "r"(b0), "r"(b1));
}

__device__ __forceinline__ uint32_t pack_bf2(__nv_bfloat16 a, __nv_bfloat16 b) {
    return ((uint32_t)__bfloat16_as_ushort(b) << 16) | (uint32_t)__bfloat16_as_ushort(a);
}

// hi/lo split convert + store 4 elems at (row, col = c4*4) into two bf16 buffers
__device__ __forceinline__ void cvt_store(char* smem, int hi_off, int lo_off,
                                          int row, int c4, float4 v) {
    __nv_bfloat16 h0 = __float2bfloat16(v.x), h1 = __float2bfloat16(v.y);
    __nv_bfloat16 h2 = __float2bfloat16(v.z), h3 = __float2bfloat16(v.w);
    __nv_bfloat16 l0 = __float2bfloat16(v.x - __bfloat162float(h0));
    __nv_bfloat16 l1 = __float2bfloat16(v.y - __bfloat162float(h1));
    __nv_bfloat16 l2 = __float2bfloat16(v.z - __bfloat162float(h2));
    __nv_bfloat16 l3 = __float2bfloat16(v.w - __bfloat162float(h3));
    const int b = (row * ASTRIDE + c4 * 4) * 2;      // 8B aligned (144*row + 8*c4)
    *(uint2*)(smem + hi_off + b) = make_uint2(pack_bf2(h0, h1), pack_bf2(h2, h3));
    *(uint2*)(smem + lo_off + b) = make_uint2(pack_bf2(l0, l1), pack_bf2(l2, l3));
}

extern "C" __global__ void __launch_bounds__(TPB, 2)
stage1_kernel(const float* __restrict__ xs, const float* __restrict__ xnb,
              const float* __restrict__ W1, const float* __restrict__ b1,
              const float* __restrict__ E1, const float* __restrict__ W2,
              const float* __restrict__ b2, int n)
{
    extern __shared__ char smem[];
    const int tid = threadIdx.x, wid = tid >> 5, lane = tid & 31;
    const int t4 = lane >> 2, tm4 = lane & 3;
    const int base = blockIdx.x * NPC;

    float* sB    = (float*)(smem + SM_BIAS);
    int*   sH    = (int*)  (smem + SM_SH);
    float* nbmax = (float*)(smem + SM_NBMAX);
    float* aggrb = (float*)(smem + SM_AGGR);
    float* hself = (float*)(smem + SM_HSELF);

    if (tid < 64) { sB[tid] = b1[tid]; sH[tid] = 0; }

    // ---- stage W1 hi/lo: [o][k], 72-stride ----
    #pragma unroll
    for (int j = 0; j < 4; ++j) {
        int idx = tid + j * TPB;              // 0..1023
        int o = idx >> 4, c4 = idx & 15;
        float4 v = __ldg((const float4*)(W1 + o * 64 + c4 * 4));
        cvt_store(smem, SM_BHI, SM_BLO, o, c4, v);
    }

    const __nv_bfloat16* Ahi = (const __nv_bfloat16*)(smem + SM_AHI);
    const __nv_bfloat16* Alo = (const __nv_bfloat16*)(smem + SM_ALO);
    const __nv_bfloat16* Bhi = (const __nv_bfloat16*)(smem + SM_BHI);
    const __nv_bfloat16* Blo = (const __nv_bfloat16*)(smem + SM_BLO);

    // ================= neighbor super-tiles: 4 x (8 nodes x 32 rows) =================
    for (int s = 0; s < 4; ++s) {
        __syncthreads();   // A buffer free (prev compute done)
        #pragma unroll
        for (int j = 0; j < 16; ++j) {
            int idx = tid + j * TPB;          // 0..4095
            int row = idx >> 4, c4 = idx & 15;
            int gn = base + s * 8 + (row >> 5); if (gn >= n) gn = n - 1;
            float4 v = __ldg((const float4*)(xnb + ((size_t)gn * KNB + (row & 31)) * 64 + c4 * 4));
            cvt_store(smem, SM_AHI, SM_ALO, row, c4, v);
        }
        __syncthreads();   // A ready

        // warp w owns node s*8+w : rows 32w..32w+31 (two m16 tiles)
        float acc[2][8][4];
        #pragma unroll
        for (int m = 0; m < 2; ++m)
            #pragma unroll
            for (int nt = 0; nt < 8; ++nt)
                #pragma unroll
                for (int q = 0; q < 4; ++q) acc[m][nt][q] = 0.f;

        #pragma unroll
        for (int pass = 0; pass < 3; ++pass) {
            const __nv_bfloat16* Ab = (pass == 2) ? Alo : Ahi;
            const __nv_bfloat16* Bb = (pass == 1) ? Blo : Bhi;
            #pragma unroll
            for (int k0 = 0; k0 < 4; ++k0) {
                const int cb = 16 * k0 + 2 * tm4;
                uint32_t bb0[8], bb1[8];
                #pragma unroll
                for (int nt = 0; nt < 8; ++nt) {
                    const __nv_bfloat16* bp = Bb + (nt * 8 + t4) * ASTRIDE + cb;
                    bb0[nt] = *(const uint32_t*)bp;
                    bb1[nt] = *(const uint32_t*)(bp + 8);
                }
                #pragma unroll
                for (int m = 0; m < 2; ++m) {
                    const __nv_bfloat16* ap = Ab + (32 * wid + 16 * m + t4) * ASTRIDE + cb;
                    uint32_t a0 = *(const uint32_t*)ap;
                    uint32_t a1 = *(const uint32_t*)(ap + 8 * ASTRIDE);
                    uint32_t a2 = *(const uint32_t*)(ap + 8);
                    uint32_t a3 = *(const uint32_t*)(ap + 8 * ASTRIDE + 8);
                    #pragma unroll
                    for (int nt = 0; nt < 8; ++nt)
                        mma16816(acc[m][nt], a0, a1, a2, a3, bb0[nt], bb1[nt]);
                }
            }
        }

        // in-warp max over the node's 32 rows; lanes 0-3 write 2 cols per n-tile
        const int node = s * 8 + wid;
        #pragma unroll
        for (int nt = 0; nt < 8; ++nt) {
            float v0 = fmaxf(fmaxf(acc[0][nt][0], acc[0][nt][2]),
                             fmaxf(acc[1][nt][0], acc[1][nt][2]));
            float v1 = fmaxf(fmaxf(acc[0][nt][1], acc[0][nt][3]),
                             fmaxf(acc[1][nt][1], acc[1][nt][3]));
            #pragma unroll
            for (int off = 4; off <= 16; off <<= 1) {
                v0 = fmaxf(v0, __shfl_xor_sync(0xffffffffu, v0, off));
                v1 = fmaxf(v1, __shfl_xor_sync(0xffffffffu, v1, off));
            }
            if (lane < 4) {
                nbmax[node * 66 + nt * 8 + 2 * lane]     = v0;
                nbmax[node * 66 + nt * 8 + 2 * lane + 1] = v1;
            }
        }
    }

    // ================= self tile: 32 rows (one per node) =================
    __syncthreads();
    #pragma unroll
    for (int j = 0; j < 2; ++j) {
        int idx = tid + j * TPB;              // 0..511
        int row = idx >> 4, c4 = idx & 15;
        int gn = base + row; if (gn >= n) gn = n - 1;
        float4 v = __ldg((const float4*)(xs + (size_t)gn * 64 + c4 * 4));
        cvt_store(smem, SM_AHI, SM_ALO, row, c4, v);
    }
    __syncthreads();

    if (wid < 2) {     // warp 0: rows 0-15, warp 1: rows 16-31
        float acc[8][4];
        #pragma unroll
        for (int nt = 0; nt < 8; ++nt)
            #pragma unroll
            for (int q = 0; q < 4; ++q) acc[nt][q] = 0.f;

        #pragma unroll
        for (int pass = 0; pass < 3; ++pass) {
            const __nv_bfloat16* Ab = (pass == 2) ? Alo : Ahi;
            const __nv_bfloat16* Bb = (pass == 1) ? Blo : Bhi;
            #pragma unroll
            for (int k0 = 0; k0 < 4; ++k0) {
                const int cb = 16 * k0 + 2 * tm4;
                const __nv_bfloat16* ap = Ab + (16 * wid + t4) * ASTRIDE + cb;
                uint32_t a0 = *(const uint32_t*)ap;
                uint32_t a1 = *(const uint32_t*)(ap + 8 * ASTRIDE);
                uint32_t a2 = *(const uint32_t*)(ap + 8);
                uint32_t a3 = *(const uint32_t*)(ap + 8 * ASTRIDE + 8);
                #pragma unroll
                for (int nt = 0; nt < 8; ++nt) {
                    const __nv_bfloat16* bp = Bb + (nt * 8 + t4) * ASTRIDE + cb;
                    uint32_t b0v = *(const uint32_t*)bp;
                    uint32_t b1v = *(const uint32_t*)(bp + 8);
                    mma16816(acc[nt], a0, a1, a2, a3, b0v, b1v);
                }
            }
        }
        const int r0 = 16 * wid + t4;
        #pragma unroll
        for (int nt = 0; nt < 8; ++nt) {
            const int c = nt * 8 + 2 * tm4;
            hself[r0 * 66 + c]           = acc[nt][0];
            hself[r0 * 66 + c + 1]       = acc[nt][1];
            hself[(r0 + 8) * 66 + c]     = acc[nt][2];
            hself[(r0 + 8) * 66 + c + 1] = acc[nt][3];
        }
    }
    __syncthreads();

    // ---- combine: aggr = relu(max(nbmax, hself) + b1) ----
    #pragma unroll
    for (int j = 0; j < 8; ++j) {
        int idx = tid + j * TPB;              // 0..2047
        int node = idx >> 6, col = idx & 63;
        aggrb[node * 66 + col] =
            fmaxf(fmaxf(nbmax[node * 66 + col], hself[node * 66 + col]) + sB[col], 0.f);
    }
    __syncthreads();

    // ---- epilogue: emb1 (l2norm) -> h2 -> block max -> global max ----
    float* embw = (float*)(smem + SM_EMBW) + wid * 80;
    for (int t = 0; t < 4; ++t) {
        const int node = wid + t * 8;
        const int gn = base + node;
        if (gn < n) {
            float a0 = 0.f, a1 = 0.f;
            const float* e0r = E1 + lane * 64;
            const float* e1r = E1 + (lane + 32) * 64;
            const float* ab  = aggrb + node * 66;
            #pragma unroll 8
            for (int d = 0; d < 64; d += 2) {
                float2 av = *(const float2*)&ab[d];
                float2 p0 = __ldg((const float2*)&e0r[d]);
                float2 p1 = __ldg((const float2*)&e1r[d]);
                a0 += av.x * p0.x + av.y * p0.y;
                a1 += av.x * p1.x + av.y * p1.y;
            }
            a0 = fmaxf(a0, 0.f); a1 = fmaxf(a1, 0.f);
            float s = a0 * a0 + a1 * a1;
            #pragma unroll
            for (int off = 16; off; off >>= 1) s += __shfl_xor_sync(0xffffffffu, s, off);
            const float inv = (s > 0.f) ? (1.0f / sqrtf(s)) : 1.0f;
            embw[lane]      = a0 * inv;
            embw[lane + 32] = a1 * inv;
            __syncwarp();
            float h0 = __ldg(&b2[lane]), h1 = __ldg(&b2[lane + 32]);
            const float* w0r = W2 + lane * 64;
            const float* w1r = W2 + (lane + 32) * 64;
            #pragma unroll 8
            for (int d = 0; d < 64; d += 2) {
                float2 ev = *(const float2*)&embw[d];
                float2 p0 = __ldg((const float2*)&w0r[d]);
                float2 p1 = __ldg((const float2*)&w1r[d]);
                h0 += ev.x * p0.x + ev.y * p0.y;
                h1 += ev.x * p1.x + ev.y * p1.y;
            }
            atomicMax(&sH[lane],      __float_as_int(h0));
            atomicMax(&sH[lane + 32], __float_as_int(h1));
            __syncwarp();
        }
    }
    __syncthreads();
    if (tid < 64) atomicMax(&g_max_bits[tid], sH[tid]);
}

// Final tiny stage: aggr2 -> emb2 (l2norm) -> regressor -> scalar out.
extern "C" __global__ void finalize_kernel(const float* __restrict__ E2,
                                           const float* __restrict__ rW1,
                                           const float* __restrict__ rb1,
                                           const float* __restrict__ rW2,
                                           const float* __restrict__ rb2,
                                           float* __restrict__ out)
{
    __shared__ float sa[64], se[64];
    __shared__ float red[2];
    const int tid = threadIdx.x;   // 64 threads

    sa[tid] = __int_as_float(g_max_bits[tid]);
    __syncthreads();

    float acc = 0.f;
    const float* er = E2 + tid * 64;
    #pragma unroll 8
    for (int d = 0; d < 64; ++d) acc += er[d] * sa[d];
    acc = fmaxf(acc, 0.f);

    float s = acc * acc;
    #pragma unroll
    for (int off = 16; off; off >>= 1) s += __shfl_xor_sync(0xffffffffu, s, off);
    if ((tid & 31) == 0) red[tid >> 5] = s;
    __syncthreads();
    const float stot = red[0] + red[1];
    const float inv = (stot > 0.f) ? (1.0f / sqrtf(stot)) : 1.0f;
    se[tid] = acc * inv;
    __syncthreads();

    float h = rb1[tid];
    const float* wr = rW1 + tid * 64;
    #pragma unroll 8
    for (int d = 0; d < 64; ++d) h += wr[d] * se[d];
    h = fmaxf(h, 0.f);

    float v = h * rW2[tid];
    #pragma unroll
    for (int off = 16; off; off >>= 1) v += __shfl_xor_sync(0xffffffffu, v, off);
    if ((tid & 31) == 0) red[tid >> 5] = v;
    __syncthreads();
    if (tid == 0) out[0] = red[0] + red[1] + rb2[0];
}

extern "C" void kernel_launch(void* const* d_in, const int* in_sizes, int n_in,
                              void* d_out, int out_size)
{
    const float* xs  = (const float*)d_in[0];
    const float* xnb = (const float*)d_in[1];
    const float* W1  = (const float*)d_in[2];
    const float* b1  = (const float*)d_in[3];
    const float* E1  = (const float*)d_in[4];
    const float* W2  = (const float*)d_in[5];
    const float* b2  = (const float*)d_in[6];
    const float* E2  = (const float*)d_in[7];
    const float* rW1 = (const float*)d_in[8];
    const float* rb1 = (const float*)d_in[9];
    const float* rW2 = (const float*)d_in[10];
    const float* rb2 = (const float*)d_in[11];

    const int n = in_sizes[0] / 64;
    const int blocks = (n + NPC - 1) / NPC;

    static int attr_done = 0;
    if (!attr_done) {
        cudaFuncSetAttribute(stage1_kernel, cudaFuncAttributeMaxDynamicSharedMemorySize, SM_TOTAL);
        attr_done = 1;
    }

    init_kernel<<<1, 64>>>();
    stage1_kernel<<<blocks, TPB, SM_TOTAL>>>(xs, xnb, W1, b1, E1, W2, b2, n);
    finalize_kernel<<<1, 64>>>(E2, rW1, rb1, rW2, rb2, (float*)d_out);
}

// round 10
// speedup vs baseline: 1.5016x; 1.0598x over previous
#include <cuda_runtime.h>
#include <cuda_bf16.h>
#include <cstdint>
#include <cstddef>

#define NPC  32            // nodes per CTA
#define TPB  512
#define KNB  32

#define ASTRIDE 72         // stage row stride: 72 fp32 (288B) / B: 72 bf16 (144B)

// ---- dynamic SMEM layout (bytes) ----
#define SM_BIAS   0                       // f32[64]
#define SM_SH     256                     // int[64]
#define SM_EMBW   512                     // 16 warps x 80 f32 (5120B)
#define SM_BHI    5632                    // W1 hi: [64][72] bf16 (9216B)
#define SM_BLO    14848                   // W1 lo: [64][72] bf16 (9216B)
#define SM_NBPART 24064                   // f32[32 nodes][2 mt][66] (16896B)
#define SM_HSELF  40960                   // f32[32][66] (8448B)
#define SM_AGGR   49408                   // f32[32][66] (8448B)
#define SM_STG0   57856                   // fp32 stage buf0: [256][72] (73728B)
#define SM_STG1   131584                  // fp32 stage buf1 (73728B)
#define SM_TOTAL  205312

__device__ int g_max_bits[64];
__global__ void init_kernel() { if (threadIdx.x < 64) g_max_bits[threadIdx.x] = 0; }

__device__ __forceinline__ void mma16816(float* d,
                                         uint32_t a0, uint32_t a1, uint32_t a2, uint32_t a3,
                                         uint32_t b0, uint32_t b1) {
    asm volatile(
        "mma.sync.aligned.m16n8k16.row.col.f32.bf16.bf16.f32 "
        "{%0,%1,%2,%3}, {%4,%5,%6,%7}, {%8,%9}, {%0,%1,%2,%3};"
        : "+f"(d[0]), "+f"(d[1]), "+f"(d[2]), "+f"(d[3])
        : "r"(a0), "r"(a1), "r"(a2), "r"(a3), "r"(b0), "r"(b1));
}

__device__ __forceinline__ uint32_t pack_bf2(__nv_bfloat16 a, __nv_bfloat16 b) {
    return ((uint32_t)__bfloat16_as_ushort(b) << 16) | (uint32_t)__bfloat16_as_ushort(a);
}

__device__ __forceinline__ void cp_async16(void* dst, const void* src) {
    unsigned s = (unsigned)__cvta_generic_to_shared(dst);
    asm volatile("cp.async.cg.shared.global [%0], [%1], 16;" :: "r"(s), "l"(src) : "memory");
}
__device__ __forceinline__ void cp_commit() {
    asm volatile("cp.async.commit_group;" ::: "memory");
}

// split an fp32 pair into packed bf16x2 hi and lo
__device__ __forceinline__ void split2(float2 v, uint32_t& hi, uint32_t& lo) {
    __nv_bfloat16 h0 = __float2bfloat16(v.x), h1 = __float2bfloat16(v.y);
    __nv_bfloat16 l0 = __float2bfloat16(v.x - __bfloat162float(h0));
    __nv_bfloat16 l1 = __float2bfloat16(v.y - __bfloat162float(h1));
    hi = pack_bf2(h0, h1);
    lo = pack_bf2(l0, l1);
}

extern "C" __global__ void __launch_bounds__(TPB, 1)
stage1_kernel(const float* __restrict__ xs, const float* __restrict__ xnb,
              const float* __restrict__ W1, const float* __restrict__ b1,
              const float* __restrict__ E1, const float* __restrict__ W2,
              const float* __restrict__ b2, int n)
{
    extern __shared__ char smem[];
    const int tid = threadIdx.x, wid = tid >> 5, lane = tid & 31;
    const int t4 = lane >> 2, tm4 = lane & 3;
    const int base = blockIdx.x * NPC;

    float* sB     = (float*)(smem + SM_BIAS);
    int*   sH     = (int*)  (smem + SM_SH);
    float* nbpart = (float*)(smem + SM_NBPART);
    float* hself  = (float*)(smem + SM_HSELF);
    float* aggrb  = (float*)(smem + SM_AGGR);

    if (tid < 64) { sB[tid] = b1[tid]; sH[tid] = 0; }

    // ---- stage W1 hi/lo bf16: [o][k], stride 72 ----
    #pragma unroll
    for (int j = 0; j < 2; ++j) {
        int idx = tid + j * TPB;              // 0..1023
        int o = idx >> 4, c4 = idx & 15;
        float4 v = __ldg((const float4*)(W1 + o * 64 + c4 * 4));
        uint32_t h01, l01, h23, l23;
        split2(make_float2(v.x, v.y), h01, l01);
        split2(make_float2(v.z, v.w), h23, l23);
        const int b = (o * ASTRIDE + c4 * 4) * 2;
        *(uint2*)(smem + SM_BHI + b) = make_uint2(h01, h23);
        *(uint2*)(smem + SM_BLO + b) = make_uint2(l01, l23);
    }

    // stage fp32 rows for tile t: t<4 -> 256 neighbor rows (nodes t*8..t*8+7); t==4 -> 32 self rows
    auto fillStage = [&](int t, char* buf) {
        if (t < 4) {
            #pragma unroll
            for (int j = 0; j < 8; ++j) {
                int idx = tid + j * TPB;      // 0..4095
                int row = idx >> 4, c4 = idx & 15;
                int gn = base + t * 8 + (row >> 5); if (gn >= n) gn = n - 1;
                cp_async16((float*)buf + row * ASTRIDE + c4 * 4,
                           xnb + ((size_t)gn * KNB + (row & 31)) * 64 + c4 * 4);
            }
        } else {
            int row = tid >> 4, c4 = tid & 15;    // 512 threads = 32 rows x 16 chunks
            int gn = base + row; if (gn >= n) gn = n - 1;
            cp_async16((float*)buf + row * ASTRIDE + c4 * 4,
                       xs + (size_t)gn * 64 + c4 * 4);
        }
        cp_commit();
    };

    const __nv_bfloat16* Bhi = (const __nv_bfloat16*)(smem + SM_BHI);
    const __nv_bfloat16* Blo = (const __nv_bfloat16*)(smem + SM_BLO);

    fillStage(0, smem + SM_STG0);

    for (int t = 0; t <= 4; ++t) {
        if (t < 4) {
            fillStage(t + 1, smem + (((t + 1) & 1) ? SM_STG1 : SM_STG0));
            asm volatile("cp.async.wait_group 1;" ::: "memory");
        } else {
            asm volatile("cp.async.wait_group 0;" ::: "memory");
        }
        __syncthreads();     // stage t ready (and B smem on t==0)

        const float* stg = (const float*)(smem + ((t & 1) ? SM_STG1 : SM_STG0));

        if (t < 4) {
            // warp: node ln = wid>>1 (0..7), m-tile mt = wid&1 (rows ln*32+mt*16 .. +15)
            const int ln = wid >> 1, mt = wid & 1;
            const int r0 = ln * 32 + mt * 16 + t4;

            float acc[8][4];
            #pragma unroll
            for (int nt = 0; nt < 8; ++nt)
                #pragma unroll
                for (int q = 0; q < 4; ++q) acc[nt][q] = 0.f;

            #pragma unroll
            for (int k0 = 0; k0 < 4; ++k0) {
                const int cb = 16 * k0 + 2 * tm4;
                // A fragments: fp32 pairs -> hi/lo bf16x2
                uint32_t ah[4], al[4];
                {
                    const float* ap = stg + r0 * ASTRIDE + cb;
                    split2(*(const float2*)ap,                     ah[0], al[0]);
                    split2(*(const float2*)(ap + 8 * ASTRIDE),     ah[1], al[1]);
                    split2(*(const float2*)(ap + 8),               ah[2], al[2]);
                    split2(*(const float2*)(ap + 8 * ASTRIDE + 8), ah[3], al[3]);
                }
                uint32_t bh0[8], bh1[8], bl0[8], bl1[8];
                #pragma unroll
                for (int nt = 0; nt < 8; ++nt) {
                    const __nv_bfloat16* bp = Bhi + (nt * 8 + t4) * ASTRIDE + cb;
                    bh0[nt] = *(const uint32_t*)bp;
                    bh1[nt] = *(const uint32_t*)(bp + 8);
                    const __nv_bfloat16* lp = Blo + (nt * 8 + t4) * ASTRIDE + cb;
                    bl0[nt] = *(const uint32_t*)lp;
                    bl1[nt] = *(const uint32_t*)(lp + 8);
                }
                #pragma unroll
                for (int nt = 0; nt < 8; ++nt) {
                    mma16816(acc[nt], ah[0], ah[1], ah[2], ah[3], bh0[nt], bh1[nt]); // xh*wh
                    mma16816(acc[nt], ah[0], ah[1], ah[2], ah[3], bl0[nt], bl1[nt]); // xh*wl
                    mma16816(acc[nt], al[0], al[1], al[2], al[3], bh0[nt], bh1[nt]); // xl*wh
                }
            }

            // max over this m-tile's 16 rows; lanes 0-3 write 2 cols per n-tile
            const int node = t * 8 + ln;
            float* dst = nbpart + (node * 2 + mt) * 66;
            #pragma unroll
            for (int nt = 0; nt < 8; ++nt) {
                float v0 = fmaxf(acc[nt][0], acc[nt][2]);
                float v1 = fmaxf(acc[nt][1], acc[nt][3]);
                #pragma unroll
                for (int off = 4; off <= 16; off <<= 1) {
                    v0 = fmaxf(v0, __shfl_xor_sync(0xffffffffu, v0, off));
                    v1 = fmaxf(v1, __shfl_xor_sync(0xffffffffu, v1, off));
                }
                if (lane < 4) {
                    dst[nt * 8 + 2 * lane]     = v0;
                    dst[nt * 8 + 2 * lane + 1] = v1;
                }
            }
        } else {
            // self tile: 32 rows, warps 0-1 (m-tile = wid)
            if (wid < 2) {
                const int r0 = 16 * wid + t4;
                float acc[8][4];
                #pragma unroll
                for (int nt = 0; nt < 8; ++nt)
                    #pragma unroll
                    for (int q = 0; q < 4; ++q) acc[nt][q] = 0.f;

                #pragma unroll
                for (int k0 = 0; k0 < 4; ++k0) {
                    const int cb = 16 * k0 + 2 * tm4;
                    uint32_t ah[4], al[4];
                    {
                        const float* ap = stg + r0 * ASTRIDE + cb;
                        split2(*(const float2*)ap,                     ah[0], al[0]);
                        split2(*(const float2*)(ap + 8 * ASTRIDE),     ah[1], al[1]);
                        split2(*(const float2*)(ap + 8),               ah[2], al[2]);
                        split2(*(const float2*)(ap + 8 * ASTRIDE + 8), ah[3], al[3]);
                    }
                    #pragma unroll
                    for (int nt = 0; nt < 8; ++nt) {
                        const __nv_bfloat16* bp = Bhi + (nt * 8 + t4) * ASTRIDE + cb;
                        uint32_t b0 = *(const uint32_t*)bp;
                        uint32_t b1 = *(const uint32_t*)(bp + 8);
                        const __nv_bfloat16* lp = Blo + (nt * 8 + t4) * ASTRIDE + cb;
                        uint32_t c0 = *(const uint32_t*)lp;
                        uint32_t c1 = *(const uint32_t*)(lp + 8);
                        mma16816(acc[nt], ah[0], ah[1], ah[2], ah[3], b0, b1);
                        mma16816(acc[nt], ah[0], ah[1], ah[2], ah[3], c0, c1);
                        mma16816(acc[nt], al[0], al[1], al[2], al[3], b0, b1);
                    }
                }
                #pragma unroll
                for (int nt = 0; nt < 8; ++nt) {
                    const int c = nt * 8 + 2 * tm4;
                    hself[r0 * 66 + c]           = acc[nt][0];
                    hself[r0 * 66 + c + 1]       = acc[nt][1];
                    hself[(r0 + 8) * 66 + c]     = acc[nt][2];
                    hself[(r0 + 8) * 66 + c + 1] = acc[nt][3];
                }
            }
        }
        __syncthreads();     // compute done before stage buffer reuse
    }

    // ---- combine: aggr = relu(max(nb_mt0, nb_mt1, hself) + b1) ----
    #pragma unroll
    for (int j = 0; j < 4; ++j) {
        int idx = tid + j * TPB;              // 0..2047
        int node = idx >> 6, col = idx & 63;
        float m = fmaxf(fmaxf(nbpart[(node * 2) * 66 + col], nbpart[(node * 2 + 1) * 66 + col]),
                        hself[node * 66 + col]);
        aggrb[node * 66 + col] = fmaxf(m + sB[col], 0.f);
    }
    __syncthreads();

    // ---- epilogue: emb1 (l2norm) -> h2 -> block max -> global max (16 warps, 32 nodes) ----
    float* embw = (float*)(smem + SM_EMBW) + wid * 80;
    for (int t = 0; t < 2; ++t) {
        const int node = wid + t * 16;
        const int gn = base + node;
        if (gn < n) {
            float a0 = 0.f, a1 = 0.f;
            const float* e0r = E1 + lane * 64;
            const float* e1r = E1 + (lane + 32) * 64;
            const float* ab  = aggrb + node * 66;
            #pragma unroll 8
            for (int d = 0; d < 64; d += 2) {
                float2 av = *(const float2*)&ab[d];
                float2 p0 = __ldg((const float2*)&e0r[d]);
                float2 p1 = __ldg((const float2*)&e1r[d]);
                a0 += av.x * p0.x + av.y * p0.y;
                a1 += av.x * p1.x + av.y * p1.y;
            }
            a0 = fmaxf(a0, 0.f); a1 = fmaxf(a1, 0.f);
            float s = a0 * a0 + a1 * a1;
            #pragma unroll
            for (int off = 16; off; off >>= 1) s += __shfl_xor_sync(0xffffffffu, s, off);
            const float inv = (s > 0.f) ? (1.0f / sqrtf(s)) : 1.0f;
            embw[lane]      = a0 * inv;
            embw[lane + 32] = a1 * inv;
            __syncwarp();
            float h0 = __ldg(&b2[lane]), h1 = __ldg(&b2[lane + 32]);
            const float* w0r = W2 + lane * 64;
            const float* w1r = W2 + (lane + 32) * 64;
            #pragma unroll 8
            for (int d = 0; d < 64; d += 2) {
                float2 ev = *(const float2*)&embw[d];
                float2 p0 = __ldg((const float2*)&w0r[d]);
                float2 p1 = __ldg((const float2*)&w1r[d]);
                h0 += ev.x * p0.x + ev.y * p0.y;
                h1 += ev.x * p1.x + ev.y * p1.y;
            }
            atomicMax(&sH[lane],      __float_as_int(h0));
            atomicMax(&sH[lane + 32], __float_as_int(h1));
            __syncwarp();
        }
    }
    __syncthreads();
    if (tid < 64) atomicMax(&g_max_bits[tid], sH[tid]);
}

// Final tiny stage: aggr2 -> emb2 (l2norm) -> regressor -> scalar out.
extern "C" __global__ void finalize_kernel(const float* __restrict__ E2,
                                           const float* __restrict__ rW1,
                                           const float* __restrict__ rb1,
                                           const float* __restrict__ rW2,
                                           const float* __restrict__ rb2,
                                           float* __restrict__ out)
{
    __shared__ float sa[64], se[64];
    __shared__ float red[2];
    const int tid = threadIdx.x;   // 64 threads

    sa[tid] = __int_as_float(g_max_bits[tid]);
    __syncthreads();

    float acc = 0.f;
    const float* er = E2 + tid * 64;
    #pragma unroll 8
    for (int d = 0; d < 64; ++d) acc += er[d] * sa[d];
    acc = fmaxf(acc, 0.f);

    float s = acc * acc;
    #pragma unroll
    for (int off = 16; off; off >>= 1) s += __shfl_xor_sync(0xffffffffu, s, off);
    if ((tid & 31) == 0) red[tid >> 5] = s;
    __syncthreads();
    const float stot = red[0] + red[1];
    const float inv = (stot > 0.f) ? (1.0f / sqrtf(stot)) : 1.0f;
    se[tid] = acc * inv;
    __syncthreads();

    float h = rb1[tid];
    const float* wr = rW1 + tid * 64;
    #pragma unroll 8
    for (int d = 0; d < 64; ++d) h += wr[d] * se[d];
    h = fmaxf(h, 0.f);

    float v = h * rW2[tid];
    #pragma unroll
    for (int off = 16; off; off >>= 1) v += __shfl_xor_sync(0xffffffffu, v, off);
    if ((tid & 31) == 0) red[tid >> 5] = v;
    __syncthreads();
    if (tid == 0) out[0] = red[0] + red[1] + rb2[0];
}

extern "C" void kernel_launch(void* const* d_in, const int* in_sizes, int n_in,
                              void* d_out, int out_size)
{
    const float* xs  = (const float*)d_in[0];
    const float* xnb = (const float*)d_in[1];
    const float* W1  = (const float*)d_in[2];
    const float* b1  = (const float*)d_in[3];
    const float* E1  = (const float*)d_in[4];
    const float* W2  = (const float*)d_in[5];
    const float* b2  = (const float*)d_in[6];
    const float* E2  = (const float*)d_in[7];
    const float* rW1 = (const float*)d_in[8];
    const float* rb1 = (const float*)d_in[9];
    const float* rW2 = (const float*)d_in[10];
    const float* rb2 = (const float*)d_in[11];

    const int n = in_sizes[0] / 64;
    const int blocks = (n + NPC - 1) / NPC;

    static int attr_done = 0;
    if (!attr_done) {
        cudaFuncSetAttribute(stage1_kernel, cudaFuncAttributeMaxDynamicSharedMemorySize, SM_TOTAL);
        attr_done = 1;
    }

    init_kernel<<<1, 64>>>();
    stage1_kernel<<<blocks, TPB, SM_TOTAL>>>(xs, xnb, W1, b1, E1, W2, b2, n);
    finalize_kernel<<<1, 64>>>(E2, rW1, rb1, rW2, rb2, (float*)d_out);
}

// round 11
// speedup vs baseline: 1.5256x; 1.0160x over previous
#include <cuda_runtime.h>
#include <cuda_fp16.h>
#include <cstdint>
#include <cstddef>

#define NPC  16            // nodes per CTA
#define TPB  256
#define KNB  32

#define ASTRIDE 72         // stage row stride: 72 fp32 / W: 72 fp16

// ---- dynamic SMEM layout (bytes) ----
#define SM_BIAS   0                       // f32[64]
#define SM_SH     256                     // int[64]
#define SM_EMBW   512                     // 8 warps x 80 f32 (2560B)
#define SM_BW     3072                    // W1 fp16: [64][72] (9216B)
#define SM_NBPART 12288                   // f32[16 nodes][2 mt][66] (8448B)
#define SM_HSELF  20736                   // f32[16][66] (4224B)
#define SM_AGGR   24960                   // f32[16][66] (4224B)
#define SM_STG0   29184                   // fp32 stage buf0: [128][72] (36864B)
#define SM_STG1   66048                   // fp32 stage buf1 (36864B)
#define SM_TOTAL  102912                  // fits 2 CTAs/SM

__device__ int g_max_bits[64];            // zero-initialized at module load; finalize re-zeros

__device__ __forceinline__ void mma16816h(float* d,
                                          uint32_t a0, uint32_t a1, uint32_t a2, uint32_t a3,
                                          uint32_t b0, uint32_t b1) {
    asm volatile(
        "mma.sync.aligned.m16n8k16.row.col.f32.f16.f16.f32 "
        "{%0,%1,%2,%3}, {%4,%5,%6,%7}, {%8,%9}, {%0,%1,%2,%3};"
        : "+f"(d[0]), "+f"(d[1]), "+f"(d[2]), "+f"(d[3])
        : "r"(a0), "r"(a1), "r"(a2), "r"(a3), "r"(b0), "r"(b1));
}

__device__ __forceinline__ void cp_async16(void* dst, const void* src) {
    unsigned s = (unsigned)__cvta_generic_to_shared(dst);
    asm volatile("cp.async.cg.shared.global [%0], [%1], 16;" :: "r"(s), "l"(src) : "memory");
}
__device__ __forceinline__ void cp_commit() {
    asm volatile("cp.async.commit_group;" ::: "memory");
}

__device__ __forceinline__ uint32_t h2_bits(__half2 h) {
    return *reinterpret_cast<uint32_t*>(&h);
}

// split an fp32 pair into fp16x2 hi and fp16x2 lo (residual)
__device__ __forceinline__ void split2h(float2 v, uint32_t& hi, uint32_t& lo) {
    __half2 h = __float22half2_rn(v);
    float2 hf = __half22float2(h);
    __half2 l = __float22half2_rn(make_float2(v.x - hf.x, v.y - hf.y));
    hi = h2_bits(h);
    lo = h2_bits(l);
}

extern "C" __global__ void __launch_bounds__(TPB, 2)
stage1_kernel(const float* __restrict__ xs, const float* __restrict__ xnb,
              const float* __restrict__ W1, const float* __restrict__ b1,
              const float* __restrict__ E1, const float* __restrict__ W2,
              const float* __restrict__ b2, int n)
{
    extern __shared__ char smem[];
    const int tid = threadIdx.x, wid = tid >> 5, lane = tid & 31;
    const int t4 = lane >> 2, tm4 = lane & 3;
    const int base = blockIdx.x * NPC;

    float* sB     = (float*)(smem + SM_BIAS);
    int*   sH     = (int*)  (smem + SM_SH);
    float* nbpart = (float*)(smem + SM_NBPART);
    float* hself  = (float*)(smem + SM_HSELF);
    float* aggrb  = (float*)(smem + SM_AGGR);

    if (tid < 64) { sB[tid] = b1[tid]; sH[tid] = 0; }

    // ---- stage W1 fp16: [o][k], stride 72 ----
    #pragma unroll
    for (int j = 0; j < 4; ++j) {
        int idx = tid + j * TPB;              // 0..1023
        int o = idx >> 4, c4 = idx & 15;
        float4 v = __ldg((const float4*)(W1 + o * 64 + c4 * 4));
        uint32_t h01 = h2_bits(__float22half2_rn(make_float2(v.x, v.y)));
        uint32_t h23 = h2_bits(__float22half2_rn(make_float2(v.z, v.w)));
        *(uint2*)(smem + SM_BW + (o * ASTRIDE + c4 * 4) * 2) = make_uint2(h01, h23);
    }

    // stage fp32 rows: t<4 -> 128 neighbor rows (nodes t*4..t*4+3); t==4 -> 16 self rows
    auto fillStage = [&](int t, char* buf) {
        if (t < 4) {
            #pragma unroll
            for (int j = 0; j < 8; ++j) {
                int idx = tid + j * TPB;      // 0..2047
                int row = idx >> 4, c4 = idx & 15;
                int gn = base + t * 4 + (row >> 5); if (gn >= n) gn = n - 1;
                cp_async16((float*)buf + row * ASTRIDE + c4 * 4,
                           xnb + ((size_t)gn * KNB + (row & 31)) * 64 + c4 * 4);
            }
        } else {
            int row = tid >> 4, c4 = tid & 15;    // 256 threads = 16 rows x 16 chunks
            int gn = base + row; if (gn >= n) gn = n - 1;
            cp_async16((float*)buf + row * ASTRIDE + c4 * 4,
                       xs + (size_t)gn * 64 + c4 * 4);
        }
        cp_commit();
    };

    const __half* Bw = (const __half*)(smem + SM_BW);

    fillStage(0, smem + SM_STG0);

    for (int t = 0; t <= 4; ++t) {
        if (t < 4) {
            fillStage(t + 1, smem + (((t + 1) & 1) ? SM_STG1 : SM_STG0));
            asm volatile("cp.async.wait_group 1;" ::: "memory");
        } else {
            asm volatile("cp.async.wait_group 0;" ::: "memory");
        }
        __syncthreads();     // stage t ready (and W smem on t==0)

        const float* stg = (const float*)(smem + ((t & 1) ? SM_STG1 : SM_STG0));

        if (t < 4) {
            // warp: node ln = wid>>1 (0..3), m-tile mt = wid&1 (rows ln*32+mt*16..+15)
            const int ln = wid >> 1, mt = wid & 1;
            const int r0 = ln * 32 + mt * 16 + t4;

            float acc[8][4];
            #pragma unroll
            for (int nt = 0; nt < 8; ++nt)
                #pragma unroll
                for (int q = 0; q < 4; ++q) acc[nt][q] = 0.f;

            #pragma unroll
            for (int k0 = 0; k0 < 4; ++k0) {
                const int cb = 16 * k0 + 2 * tm4;
                uint32_t ah[4], al[4];
                {
                    const float* ap = stg + r0 * ASTRIDE + cb;
                    split2h(*(const float2*)ap,                     ah[0], al[0]);
                    split2h(*(const float2*)(ap + 8 * ASTRIDE),     ah[1], al[1]);
                    split2h(*(const float2*)(ap + 8),               ah[2], al[2]);
                    split2h(*(const float2*)(ap + 8 * ASTRIDE + 8), ah[3], al[3]);
                }
                uint32_t bv0[8], bv1[8];
                #pragma unroll
                for (int nt = 0; nt < 8; ++nt) {
                    const __half* bp = Bw + (nt * 8 + t4) * ASTRIDE + cb;
                    bv0[nt] = *(const uint32_t*)bp;
                    bv1[nt] = *(const uint32_t*)(bp + 8);
                }
                #pragma unroll
                for (int nt = 0; nt < 8; ++nt) {
                    mma16816h(acc[nt], ah[0], ah[1], ah[2], ah[3], bv0[nt], bv1[nt]); // xh*w
                    mma16816h(acc[nt], al[0], al[1], al[2], al[3], bv0[nt], bv1[nt]); // xl*w
                }
            }

            // max over this m-tile's 16 rows; lanes 0-3 write 2 cols per n-tile
            const int node = t * 4 + ln;
            float* dst = nbpart + (node * 2 + mt) * 66;
            #pragma unroll
            for (int nt = 0; nt < 8; ++nt) {
                float v0 = fmaxf(acc[nt][0], acc[nt][2]);
                float v1 = fmaxf(acc[nt][1], acc[nt][3]);
                #pragma unroll
                for (int off = 4; off <= 16; off <<= 1) {
                    v0 = fmaxf(v0, __shfl_xor_sync(0xffffffffu, v0, off));
                    v1 = fmaxf(v1, __shfl_xor_sync(0xffffffffu, v1, off));
                }
                if (lane < 4) {
                    dst[nt * 8 + 2 * lane]     = v0;
                    dst[nt * 8 + 2 * lane + 1] = v1;
                }
            }
        } else {
            // self tile: 16 rows x 64 cols; warp w computes n-tile nt=w (m16n8)
            float acc[4] = {0.f, 0.f, 0.f, 0.f};
            #pragma unroll
            for (int k0 = 0; k0 < 4; ++k0) {
                const int cb = 16 * k0 + 2 * tm4;
                uint32_t ah[4], al[4];
                {
                    const float* ap = stg + t4 * ASTRIDE + cb;
                    split2h(*(const float2*)ap,                     ah[0], al[0]);
                    split2h(*(const float2*)(ap + 8 * ASTRIDE),     ah[1], al[1]);
                    split2h(*(const float2*)(ap + 8),               ah[2], al[2]);
                    split2h(*(const float2*)(ap + 8 * ASTRIDE + 8), ah[3], al[3]);
                }
                const __half* bp = Bw + (wid * 8 + t4) * ASTRIDE + cb;
                uint32_t b0 = *(const uint32_t*)bp;
                uint32_t b1 = *(const uint32_t*)(bp + 8);
                mma16816h(acc, ah[0], ah[1], ah[2], ah[3], b0, b1);
                mma16816h(acc, al[0], al[1], al[2], al[3], b0, b1);
            }
            const int c = wid * 8 + 2 * tm4;
            hself[t4 * 66 + c]           = acc[0];
            hself[t4 * 66 + c + 1]       = acc[1];
            hself[(t4 + 8) * 66 + c]     = acc[2];
            hself[(t4 + 8) * 66 + c + 1] = acc[3];
        }
        __syncthreads();     // compute done before stage buffer reuse
    }

    // ---- combine: aggr = relu(max(nb_mt0, nb_mt1, hself) + b1) ----
    #pragma unroll
    for (int j = 0; j < 4; ++j) {
        int idx = tid + j * TPB;              // 0..1023
        int node = idx >> 6, col = idx & 63;
        float m = fmaxf(fmaxf(nbpart[(node * 2) * 66 + col], nbpart[(node * 2 + 1) * 66 + col]),
                        hself[node * 66 + col]);
        aggrb[node * 66 + col] = fmaxf(m + sB[col], 0.f);
    }
    __syncthreads();

    // ---- epilogue: emb1 (l2norm) -> h2 -> block max -> global max (8 warps, 16 nodes) ----
    float* embw = (float*)(smem + SM_EMBW) + wid * 80;
    for (int t = 0; t < 2; ++t) {
        const int node = wid + t * 8;
        const int gn = base + node;
        if (gn < n) {
            float a0 = 0.f, a1 = 0.f;
            const float* e0r = E1 + lane * 64;
            const float* e1r = E1 + (lane + 32) * 64;
            const float* ab  = aggrb + node * 66;
            #pragma unroll 8
            for (int d = 0; d < 64; d += 2) {
                float2 av = *(const float2*)&ab[d];
                float2 p0 = __ldg((const float2*)&e0r[d]);
                float2 p1 = __ldg((const float2*)&e1r[d]);
                a0 += av.x * p0.x + av.y * p0.y;
                a1 += av.x * p1.x + av.y * p1.y;
            }
            a0 = fmaxf(a0, 0.f); a1 = fmaxf(a1, 0.f);
            float s = a0 * a0 + a1 * a1;
            #pragma unroll
            for (int off = 16; off; off >>= 1) s += __shfl_xor_sync(0xffffffffu, s, off);
            const float inv = (s > 0.f) ? (1.0f / sqrtf(s)) : 1.0f;
            embw[lane]      = a0 * inv;
            embw[lane + 32] = a1 * inv;
            __syncwarp();
            float h0 = __ldg(&b2[lane]), h1 = __ldg(&b2[lane + 32]);
            const float* w0r = W2 + lane * 64;
            const float* w1r = W2 + (lane + 32) * 64;
            #pragma unroll 8
            for (int d = 0; d < 64; d += 2) {
                float2 ev = *(const float2*)&embw[d];
                float2 p0 = __ldg((const float2*)&w0r[d]);
                float2 p1 = __ldg((const float2*)&w1r[d]);
                h0 += ev.x * p0.x + ev.y * p0.y;
                h1 += ev.x * p1.x + ev.y * p1.y;
            }
            atomicMax(&sH[lane],      __float_as_int(h0));
            atomicMax(&sH[lane + 32], __float_as_int(h1));
            __syncwarp();
        }
    }
    __syncthreads();
    if (tid < 64) atomicMax(&g_max_bits[tid], sH[tid]);
}

// Final tiny stage: aggr2 -> emb2 (l2norm) -> regressor -> scalar out.
// Also resets g_max_bits for the next call (device global starts zeroed at load).
extern "C" __global__ void finalize_kernel(const float* __restrict__ E2,
                                           const float* __restrict__ rW1,
                                           const float* __restrict__ rb1,
                                           const float* __restrict__ rW2,
                                           const float* __restrict__ rb2,
                                           float* __restrict__ out)
{
    __shared__ float sa[64], se[64];
    __shared__ float red[2];
    const int tid = threadIdx.x;   // 64 threads

    sa[tid] = __int_as_float(g_max_bits[tid]);
    __syncthreads();
    g_max_bits[tid] = 0;           // reset for next launch sequence

    float acc = 0.f;
    const float* er = E2 + tid * 64;
    #pragma unroll 8
    for (int d = 0; d < 64; ++d) acc += er[d] * sa[d];
    acc = fmaxf(acc, 0.f);

    float s = acc * acc;
    #pragma unroll
    for (int off = 16; off; off >>= 1) s += __shfl_xor_sync(0xffffffffu, s, off);
    if ((tid & 31) == 0) red[tid >> 5] = s;
    __syncthreads();
    const float stot = red[0] + red[1];
    const float inv = (stot > 0.f) ? (1.0f / sqrtf(stot)) : 1.0f;
    se[tid] = acc * inv;
    __syncthreads();

    float h = rb1[tid];
    const float* wr = rW1 + tid * 64;
    #pragma unroll 8
    for (int d = 0; d < 64; ++d) h += wr[d] * se[d];
    h = fmaxf(h, 0.f);

    float v = h * rW2[tid];
    #pragma unroll
    for (int off = 16; off; off >>= 1) v += __shfl_xor_sync(0xffffffffu, v, off);
    if ((tid & 31) == 0) red[tid >> 5] = v;
    __syncthreads();
    if (tid == 0) out[0] = red[0] + red[1] + rb2[0];
}

extern "C" void kernel_launch(void* const* d_in, const int* in_sizes, int n_in,
                              void* d_out, int out_size)
{
    const float* xs  = (const float*)d_in[0];
    const float* xnb = (const float*)d_in[1];
    const float* W1  = (const float*)d_in[2];
    const float* b1  = (const float*)d_in[3];
    const float* E1  = (const float*)d_in[4];
    const float* W2  = (const float*)d_in[5];
    const float* b2  = (const float*)d_in[6];
    const float* E2  = (const float*)d_in[7];
    const float* rW1 = (const float*)d_in[8];
    const float* rb1 = (const float*)d_in[9];
    const float* rW2 = (const float*)d_in[10];
    const float* rb2 = (const float*)d_in[11];

    const int n = in_sizes[0] / 64;
    const int blocks = (n + NPC - 1) / NPC;

    static int attr_done = 0;
    if (!attr_done) {
        cudaFuncSetAttribute(stage1_kernel, cudaFuncAttributeMaxDynamicSharedMemorySize, SM_TOTAL);
        attr_done = 1;
    }

    stage1_kernel<<<blocks, TPB, SM_TOTAL>>>(xs, xnb, W1, b1, E1, W2, b2, n);
    finalize_kernel<<<1, 64>>>(E2, rW1, rb1, rW2, rb2, (float*)d_out);
}

// round 13
// speedup vs baseline: 9.1884x; 6.0227x over previous
#include <cuda_runtime.h>
#include <cuda_fp16.h>
#include <cstdint>
#include <cstddef>

#define NPC  16            // nodes per CTA
#define TPB  256
#define KNB  32

#define ASTRIDE 72         // stage row stride fp32 / W1 fp16

// ---- dynamic SMEM layout (bytes) ----
#define SM_BIAS   0                       // b1 f32[64]
#define SM_B2S    256                     // b2 f32[64]
#define SM_INV    512                     // inv-norm f32[16]
#define SM_BW     3072                    // W1 fp16: [64][72] (9216B)
#define SM_NBPART 12288                   // f32[16 nodes][2 mt][66] (8448B); reused as ynorm [16][68]
#define SM_HSELF  20736                   // f32[16][66] (4224B)
#define SM_AGGR   24960                   // f32[16][66] (4224B)
#define SM_STG0   29184                   // fp32 stage buf0: [128][72] (36864B)
#define SM_STG1   66048                   // fp32 stage buf1 (36864B); reused for E1F/W2F
#define SM_TOTAL  102912                  // 2 CTAs/SM

#define SM_E1F    SM_STG1                 // E1 fp32 [64][68] (17408B)
#define SM_W2F    (SM_STG1 + 17408)       // W2 fp32 [64][68] (17408B)
#define SM_YN     SM_NBPART               // ynorm f32 [16][68]

__device__ int g_max_bits[64];            // zero at load; reset_kernel re-zeros each call

__device__ __forceinline__ void mma16816h(float* d,
                                          uint32_t a0, uint32_t a1, uint32_t a2, uint32_t a3,
                                          uint32_t b0, uint32_t b1) {
    asm volatile(
        "mma.sync.aligned.m16n8k16.row.col.f32.f16.f16.f32 "
        "{%0,%1,%2,%3}, {%4,%5,%6,%7}, {%8,%9}, {%0,%1,%2,%3};"
        : "+f"(d[0]), "+f"(d[1]), "+f"(d[2]), "+f"(d[3])
        : "r"(a0), "r"(a1), "r"(a2), "r"(a3), "r"(b0), "r"(b1));
}

__device__ __forceinline__ void cp_async16(void* dst, const void* src) {
    unsigned s = (unsigned)__cvta_generic_to_shared(dst);
    asm volatile("cp.async.cg.shared.global [%0], [%1], 16;" :: "r"(s), "l"(src) : "memory");
}
__device__ __forceinline__ void cp_commit() {
    asm volatile("cp.async.commit_group;" ::: "memory");
}

__device__ __forceinline__ uint32_t h2_bits(__half2 h) {
    return *reinterpret_cast<uint32_t*>(&h);
}
__device__ __forceinline__ uint32_t cvt_h2(float2 v) {
    return h2_bits(__float22half2_rn(v));
}
// split fp32 pair into fp16x2 hi + residual lo
__device__ __forceinline__ void split2h(float2 v, uint32_t& hi, uint32_t& lo) {
    __half2 h = __float22half2_rn(v);
    float2 hf = __half22float2(h);
    __half2 l = __float22half2_rn(make_float2(v.x - hf.x, v.y - hf.y));
    hi = h2_bits(h);
    lo = h2_bits(l);
}

extern "C" __global__ void __launch_bounds__(TPB, 2)
stage1_kernel(const float* __restrict__ xs, const float* __restrict__ xnb,
              const float* __restrict__ W1, const float* __restrict__ b1,
              const float* __restrict__ E1, const float* __restrict__ W2,
              const float* __restrict__ b2, int n)
{
    extern __shared__ char smem[];
    const int tid = threadIdx.x, wid = tid >> 5, lane = tid & 31;
    const int t4 = lane >> 2, tm4 = lane & 3;
    const int base = blockIdx.x * NPC;

    float* sB     = (float*)(smem + SM_BIAS);
    float* sB2    = (float*)(smem + SM_B2S);
    float* sInv   = (float*)(smem + SM_INV);
    float* nbpart = (float*)(smem + SM_NBPART);
    float* hself  = (float*)(smem + SM_HSELF);
    float* aggrb  = (float*)(smem + SM_AGGR);
    float* ynorm  = (float*)(smem + SM_YN);
    const float* E1F = (const float*)(smem + SM_E1F);
    const float* W2F = (const float*)(smem + SM_W2F);

    if (tid < 64) sB[tid] = b1[tid];
    else if (tid < 128) sB2[tid - 64] = b2[tid - 64];

    // ---- stage W1 fp16: [o][k], stride 72 ----
    #pragma unroll
    for (int j = 0; j < 4; ++j) {
        int idx = tid + j * TPB;              // 0..1023
        int o = idx >> 4, c4 = idx & 15;
        float4 v = __ldg((const float4*)(W1 + o * 64 + c4 * 4));
        *(uint2*)(smem + SM_BW + (o * ASTRIDE + c4 * 4) * 2) =
            make_uint2(cvt_h2(make_float2(v.x, v.y)), cvt_h2(make_float2(v.z, v.w)));
    }

    // stage fp32 rows: t<4 -> 128 neighbor rows (nodes t*4..t*4+3); t==4 -> 16 self rows
    auto fillStage = [&](int t, char* buf) {
        if (t < 4) {
            #pragma unroll
            for (int j = 0; j < 8; ++j) {
                int idx = tid + j * TPB;      // 0..2047
                int row = idx >> 4, c4 = idx & 15;
                int gn = base + t * 4 + (row >> 5); if (gn >= n) gn = n - 1;
                cp_async16((float*)buf + row * ASTRIDE + c4 * 4,
                           xnb + ((size_t)gn * KNB + (row & 31)) * 64 + c4 * 4);
            }
        } else {
            int row = tid >> 4, c4 = tid & 15;
            int gn = base + row; if (gn >= n) gn = n - 1;
            cp_async16((float*)buf + row * ASTRIDE + c4 * 4,
                       xs + (size_t)gn * 64 + c4 * 4);
        }
        cp_commit();
    };

    const __half* Bw = (const __half*)(smem + SM_BW);

    fillStage(0, smem + SM_STG0);

    for (int t = 0; t <= 4; ++t) {
        if (t < 4) {
            fillStage(t + 1, smem + (((t + 1) & 1) ? SM_STG1 : SM_STG0));
            asm volatile("cp.async.wait_group 1;" ::: "memory");
        } else {
            asm volatile("cp.async.wait_group 0;" ::: "memory");
        }
        __syncthreads();     // stage t ready

        if (t == 4) {
            // prefetch E1/W2 fp32 into padded [64][68] (STG1 free now); overlaps self compute
            #pragma unroll
            for (int j = 0; j < 4; ++j) {
                int idx = tid + j * TPB;      // 0..1023
                int row = idx >> 4, c4 = idx & 15;
                cp_async16((float*)(smem + SM_E1F) + row * 68 + c4 * 4, E1 + row * 64 + c4 * 4);
            }
            #pragma unroll
            for (int j = 0; j < 4; ++j) {
                int idx = tid + j * TPB;
                int row = idx >> 4, c4 = idx & 15;
                cp_async16((float*)(smem + SM_W2F) + row * 68 + c4 * 4, W2 + row * 64 + c4 * 4);
            }
            cp_commit();
        }

        const float* stg = (const float*)(smem + ((t & 1) ? SM_STG1 : SM_STG0));

        if (t < 4) {
            const int ln = wid >> 1, mt = wid & 1;
            const int r0 = ln * 32 + mt * 16 + t4;

            float acc[8][4];
            #pragma unroll
            for (int nt = 0; nt < 8; ++nt)
                #pragma unroll
                for (int q = 0; q < 4; ++q) acc[nt][q] = 0.f;

            #pragma unroll
            for (int k0 = 0; k0 < 4; ++k0) {
                const int cb = 16 * k0 + 2 * tm4;
                uint32_t ah[4], al[4];
                {
                    const float* ap = stg + r0 * ASTRIDE + cb;
                    split2h(*(const float2*)ap,                     ah[0], al[0]);
                    split2h(*(const float2*)(ap + 8 * ASTRIDE),     ah[1], al[1]);
                    split2h(*(const float2*)(ap + 8),               ah[2], al[2]);
                    split2h(*(const float2*)(ap + 8 * ASTRIDE + 8), ah[3], al[3]);
                }
                uint32_t bv0[8], bv1[8];
                #pragma unroll
                for (int nt = 0; nt < 8; ++nt) {
                    const __half* bp = Bw + (nt * 8 + t4) * ASTRIDE + cb;
                    bv0[nt] = *(const uint32_t*)bp;
                    bv1[nt] = *(const uint32_t*)(bp + 8);
                }
                #pragma unroll
                for (int nt = 0; nt < 8; ++nt) {
                    mma16816h(acc[nt], ah[0], ah[1], ah[2], ah[3], bv0[nt], bv1[nt]);
                    mma16816h(acc[nt], al[0], al[1], al[2], al[3], bv0[nt], bv1[nt]);
                }
            }

            const int node = t * 4 + ln;
            float* dst = nbpart + (node * 2 + mt) * 66;
            #pragma unroll
            for (int nt = 0; nt < 8; ++nt) {
                float v0 = fmaxf(acc[nt][0], acc[nt][2]);
                float v1 = fmaxf(acc[nt][1], acc[nt][3]);
                #pragma unroll
                for (int off = 4; off <= 16; off <<= 1) {
                    v0 = fmaxf(v0, __shfl_xor_sync(0xffffffffu, v0, off));
                    v1 = fmaxf(v1, __shfl_xor_sync(0xffffffffu, v1, off));
                }
                if (lane < 4) {
                    dst[nt * 8 + 2 * lane]     = v0;
                    dst[nt * 8 + 2 * lane + 1] = v1;
                }
            }
        } else {
            // self tile: 16 rows x 64 cols; warp w computes n-tile nt=w
            float acc[4] = {0.f, 0.f, 0.f, 0.f};
            #pragma unroll
            for (int k0 = 0; k0 < 4; ++k0) {
                const int cb = 16 * k0 + 2 * tm4;
                uint32_t ah[4], al[4];
                {
                    const float* ap = stg + t4 * ASTRIDE + cb;
                    split2h(*(const float2*)ap,                     ah[0], al[0]);
                    split2h(*(const float2*)(ap + 8 * ASTRIDE),     ah[1], al[1]);
                    split2h(*(const float2*)(ap + 8),               ah[2], al[2]);
                    split2h(*(const float2*)(ap + 8 * ASTRIDE + 8), ah[3], al[3]);
                }
                const __half* bp = Bw + (wid * 8 + t4) * ASTRIDE + cb;
                uint32_t b0 = *(const uint32_t*)bp;
                uint32_t b1 = *(const uint32_t*)(bp + 8);
                mma16816h(acc, ah[0], ah[1], ah[2], ah[3], b0, b1);
                mma16816h(acc, al[0], al[1], al[2], al[3], b0, b1);
            }
            const int c = wid * 8 + 2 * tm4;
            hself[t4 * 66 + c]           = acc[0];
            hself[t4 * 66 + c + 1]       = acc[1];
            hself[(t4 + 8) * 66 + c]     = acc[2];
            hself[(t4 + 8) * 66 + c + 1] = acc[3];
        }
        __syncthreads();
    }

    // ---- combine: aggr = relu(max(nb_mt0, nb_mt1, hself) + b1) ----
    #pragma unroll
    for (int j = 0; j < 4; ++j) {
        int idx = tid + j * TPB;              // 0..1023
        int node = idx >> 6, col = idx & 63;
        float m = fmaxf(fmaxf(nbpart[(node * 2) * 66 + col], nbpart[(node * 2 + 1) * 66 + col]),
                        hself[node * 66 + col]);
        aggrb[node * 66 + col] = fmaxf(m + sB[col], 0.f);
    }
    asm volatile("cp.async.wait_group 0;" ::: "memory");   // E1F/W2F arrived (per-thread)
    __syncthreads();                                       // aggrb + E1F/W2F visible to all

    // ---- MMA epilogue 1: y1 = relu(aggr @ E1^T), [16 x 64]; warp w -> n-tile w ----
    {
        float acc[4] = {0.f, 0.f, 0.f, 0.f};
        #pragma unroll
        for (int k0 = 0; k0 < 4; ++k0) {
            const int cb = 16 * k0 + 2 * tm4;
            uint32_t ah[4], al[4];
            {
                const float* ap = aggrb + t4 * 66 + cb;
                split2h(*(const float2*)ap,                ah[0], al[0]);
                split2h(*(const float2*)(ap + 8 * 66),     ah[1], al[1]);
                split2h(*(const float2*)(ap + 8),          ah[2], al[2]);
                split2h(*(const float2*)(ap + 8 * 66 + 8), ah[3], al[3]);
            }
            const float* bp = E1F + (wid * 8 + t4) * 68 + cb;
            uint32_t b0 = cvt_h2(*(const float2*)bp);
            uint32_t b1 = cvt_h2(*(const float2*)(bp + 8));
            mma16816h(acc, ah[0], ah[1], ah[2], ah[3], b0, b1);
            mma16816h(acc, al[0], al[1], al[2], al[3], b0, b1);
        }
        __syncthreads();   // nbpart fully consumed by combine; safe to overwrite as ynorm
        const int c = wid * 8 + 2 * tm4;
        *(float2*)(ynorm + t4 * 68 + c)       = make_float2(fmaxf(acc[0], 0.f), fmaxf(acc[1], 0.f));
        *(float2*)(ynorm + (t4 + 8) * 68 + c) = make_float2(fmaxf(acc[2], 0.f), fmaxf(acc[3], 0.f));
    }
    __syncthreads();

    // ---- per-node inverse L2 norm: warp w -> nodes w, w+8 ----
    {
        #pragma unroll
        for (int h = 0; h < 2; ++h) {
            const int node = wid + h * 8;
            float2 y = *(const float2*)(ynorm + node * 68 + 2 * lane);
            float s = y.x * y.x + y.y * y.y;
            #pragma unroll
            for (int off = 16; off; off >>= 1) s += __shfl_xor_sync(0xffffffffu, s, off);
            if (lane == 0) sInv[node] = (s > 0.f) ? (1.0f / sqrtf(s)) : 1.0f;
        }
    }
    __syncthreads();

    // ---- MMA epilogue 2: h2 = (y1*inv) @ W2^T + b2; max over 16 nodes -> global max ----
    {
        const float i0 = sInv[t4], i1 = sInv[t4 + 8];
        float acc[4] = {0.f, 0.f, 0.f, 0.f};
        #pragma unroll
        for (int k0 = 0; k0 < 4; ++k0) {
            const int cb = 16 * k0 + 2 * tm4;
            uint32_t ah[4], al[4];
            {
                const float* ap = ynorm + t4 * 68 + cb;
                float2 v0 = *(const float2*)ap;
                float2 v1 = *(const float2*)(ap + 8 * 68);
                float2 v2 = *(const float2*)(ap + 8);
                float2 v3 = *(const float2*)(ap + 8 * 68 + 8);
                split2h(make_float2(v0.x * i0, v0.y * i0), ah[0], al[0]);
                split2h(make_float2(v1.x * i1, v1.y * i1), ah[1], al[1]);
                split2h(make_float2(v2.x * i0, v2.y * i0), ah[2], al[2]);
                split2h(make_float2(v3.x * i1, v3.y * i1), ah[3], al[3]);
            }
            const float* bp = W2F + (wid * 8 + t4) * 68 + cb;
            uint32_t b0 = cvt_h2(*(const float2*)bp);
            uint32_t b1 = cvt_h2(*(const float2*)(bp + 8));
            mma16816h(acc, ah[0], ah[1], ah[2], ah[3], b0, b1);
            mma16816h(acc, al[0], al[1], al[2], al[3], b0, b1);
        }
        // max over 16 rows (nodes): in-reg rows t4/t4+8, then reduce over t4
        float v0 = fmaxf(acc[0], acc[2]);
        float v1 = fmaxf(acc[1], acc[3]);
        #pragma unroll
        for (int off = 4; off <= 16; off <<= 1) {
            v0 = fmaxf(v0, __shfl_xor_sync(0xffffffffu, v0, off));
            v1 = fmaxf(v1, __shfl_xor_sync(0xffffffffu, v1, off));
        }
        if (lane < 4) {
            const int c = wid * 8 + 2 * lane;
            atomicMax(&g_max_bits[c],     __float_as_int(v0 + sB2[c]));
            atomicMax(&g_max_bits[c + 1], __float_as_int(v1 + sB2[c + 1]));
        }
    }
}

// Final tiny stage: aggr2 -> emb2 (l2norm) -> regressor -> scalar out.
extern "C" __global__ void finalize_kernel(const float* __restrict__ E2,
                                           const float* __restrict__ rW1,
                                           const float* __restrict__ rb1,
                                           const float* __restrict__ rW2,
                                           const float* __restrict__ rb2,
                                           float* __restrict__ out)
{
    __shared__ float sa[64], se[64];
    __shared__ float red[2];
    const int tid = threadIdx.x;   // 64 threads

    sa[tid] = __int_as_float(g_max_bits[tid]);   // relu(max h2+b2) via 0-init floor
    __syncthreads();

    float acc = 0.f;
    const float* er = E2 + tid * 64;
    #pragma unroll 8
    for (int d = 0; d < 64; ++d) acc += er[d] * sa[d];
    acc = fmaxf(acc, 0.f);

    float s = acc * acc;
    #pragma unroll
    for (int off = 16; off; off >>= 1) s += __shfl_xor_sync(0xffffffffu, s, off);
    if ((tid & 31) == 0) red[tid >> 5] = s;
    __syncthreads();
    const float stot = red[0] + red[1];
    const float inv = (stot > 0.f) ? (1.0f / sqrtf(stot)) : 1.0f;
    se[tid] = acc * inv;
    __syncthreads();

    float h = rb1[tid];
    const float* wr = rW1 + tid * 64;
    #pragma unroll 8
    for (int d = 0; d < 64; ++d) h += wr[d] * se[d];
    h = fmaxf(h, 0.f);

    float v = h * rW2[tid];
    #pragma unroll
    for (int off = 16; off; off >>= 1) v += __shfl_xor_sync(0xffffffffu, v, off);
    if ((tid & 31) == 0) red[tid >> 5] = v;
    __syncthreads();
    if (tid == 0) out[0] = red[0] + red[1] + rb2[0];
}

// Reset accumulator for the next replay (3rd launch; also fixes ncu slot onto stage1).
extern "C" __global__ void reset_kernel() {
    if (threadIdx.x < 64) g_max_bits[threadIdx.x] = 0;
}

extern "C" void kernel_launch(void* const* d_in, const int* in_sizes, int n_in,
                              void* d_out, int out_size)
{
    const float* xs  = (const float*)d_in[0];
    const float* xnb = (const float*)d_in[1];
    const float* W1  = (const float*)d_in[2];
    const float* b1  = (const float*)d_in[3];
    const float* E1  = (const float*)d_in[4];
    const float* W2  = (const float*)d_in[5];
    const float* b2  = (const float*)d_in[6];
    const float* E2  = (const float*)d_in[7];
    const float* rW1 = (const float*)d_in[8];
    const float* rb1 = (const float*)d_in[9];
    const float* rW2 = (const float*)d_in[10];
    const float* rb2 = (const float*)d_in[11];

    const int n = in_sizes[0] / 64;
    const int blocks = (n + NPC - 1) / NPC;

    static int attr_done = 0;
    if (!attr_done) {
        cudaFuncSetAttribute(stage1_kernel, cudaFuncAttributeMaxDynamicSharedMemorySize, SM_TOTAL);
        attr_done = 1;
    }

    stage1_kernel<<<blocks, TPB, SM_TOTAL>>>(xs, xnb, W1, b1, E1, W2, b2, n);
    finalize_kernel<<<1, 64>>>(E2, rW1, rb1, rW2, rb2, (float*)d_out);
    reset_kernel<<<1, 64>>>();
}